// round 4
// baseline (speedup 1.0000x reference)
#include <cuda_runtime.h>
#include <math.h>

// ---------------------------------------------------------------------------
// Butterfly module, round 3 (resubmit after infra failure).
//
// Layout: CTA = 16-row block x 512 cols, 256 threads.
//   Phase 1 (row-split): lanes 0-15 hold rows 0-7, lanes 16-31 rows 8-15,
//     each as 8 x float4. Strides 1,2,4 thread-local.
//   Column swap (16 shuffles): partner = lane^16. Thread keeps 2 of its 4
//     columns for ALL 16 rows -> 16 x float2 (32 regs). All remaining layers
//     (s8, activation, s1,s2,s4,s8) are thread-local.
//   Swap back (16 shuffles) -> coalesced float4 stores.
//
// cos/sin precomputed into a device table by a prep kernel (keeps sincosf's
// register-hungry slow path out of the hot kernel).
// ---------------------------------------------------------------------------

#define CURV2 0.01f   // CURVATURE^2

__device__ float2        g_cs[1 << 15];       // [layer * N/2 + pair] -> (cos, sin)
__device__ unsigned char g_covered[1 << 20];  // scatter coverage flags (init 0)

__device__ __forceinline__ float smooth_relu(float xa) {
    return 0.5f * (xa + sqrtf(fmaf(xa, xa, CURV2)));
}

__device__ __forceinline__ void rot4(float4& a, float4& b, float c, float s) {
    float4 na, nb;
    na.x = fmaf(c, a.x, s * b.x);  nb.x = fmaf(c, b.x, -s * a.x);
    na.y = fmaf(c, a.y, s * b.y);  nb.y = fmaf(c, b.y, -s * a.y);
    na.z = fmaf(c, a.z, s * b.z);  nb.z = fmaf(c, b.z, -s * a.z);
    na.w = fmaf(c, a.w, s * b.w);  nb.w = fmaf(c, b.w, -s * a.w);
    a = na; b = nb;
}

__device__ __forceinline__ void rot2(float2& l, float2& h, float2 cs) {
    float2 nl, nh;
    nl.x = fmaf(cs.x, l.x, cs.y * h.x);  nh.x = fmaf(cs.x, h.x, -cs.y * l.x);
    nl.y = fmaf(cs.x, l.y, cs.y * h.y);  nh.y = fmaf(cs.x, h.y, -cs.y * l.y);
    l = nl; h = nh;
}

// Row-split layer over an 8-row half, stride S in {1,2,4}. cs pre-offset by
// 4*half so local rank + 4*half = global ascending-low rank.
template <int S>
__device__ __forceinline__ void blayer8(float4 v[8], const float2* __restrict__ cs) {
    int p = 0;
#pragma unroll
    for (int i = 0; i < 8; ++i)
        if ((i & S) == 0) { float2 a = cs[p++]; rot4(v[i], v[i + S], a.x, a.y); }
}

// Full 16-row layer on float2 columns, global ascending-low ranks.
template <int S>
__device__ __forceinline__ void blayer16(float2 a[16], const float2* __restrict__ cs) {
    int p = 0;
#pragma unroll
    for (int o = 0; o < 16; ++o)
        if ((o & S) == 0) { rot2(a[o], a[o + S], cs[p++]); }
}

__global__ __launch_bounds__(256)
void butterfly_kernel(const float* __restrict__ data,
                      const float* __restrict__ biases,
                      const int*   __restrict__ idx_in,
                      const int*   __restrict__ idx_out,
                      float*       __restrict__ out,
                      int N, int B)
{
    __shared__ float2 cs[64];
    __shared__ float  sb[8];
    __shared__ int    rin[16], rout[16];

    const int tid = threadIdx.x;
    const int blk = blockIdx.y;

    if (tid < 64) {
        int l = tid >> 3, p = tid & 7;
        cs[tid] = g_cs[l * (N >> 1) + blk * 8 + p];
    }
    if (tid < 8)  sb[tid] = biases[blk * 8 + tid];
    if (tid < 16) {
        rin[tid]  = idx_in[blk * 16 + tid];
        rout[tid] = idx_out[blk * 16 + tid];
    }
    __syncthreads();

    const int lane  = tid & 31;
    const int half  = lane >> 4;                       // 0: rows 0-7, 1: rows 8-15
    const int c4    = (tid >> 5) * 16 + (lane & 15);   // float4 column in tile
    const int col   = blockIdx.x * 512 + c4 * 4;
    const int rbase = half * 8;

    // --- load 8 rows x float4 (row-split) ---
    float4 v[8];
#pragma unroll
    for (int i = 0; i < 8; ++i)
        v[i] = *reinterpret_cast<const float4*>(
                   data + (size_t)rin[rbase + i] * B + col);

    // --- input layers, strides 1,2,4 (row-split, local) ---
    const float2* c0 = cs + 4 * half;
    blayer8<1>(v, c0 + 0);
    blayer8<2>(v, c0 + 8);
    blayer8<4>(v, c0 + 16);

    // --- column swap: -> 16 rows x float2 per thread ---
    // half0 keeps cols {0,1}, sends {2,3}; half1 keeps {2,3}, sends {0,1}.
    float2 a[16];
#pragma unroll
    for (int i = 0; i < 8; ++i) {
        float2 send = half ? make_float2(v[i].x, v[i].y)
                           : make_float2(v[i].z, v[i].w);
        float2 keep = half ? make_float2(v[i].z, v[i].w)
                           : make_float2(v[i].x, v[i].y);
        float2 recv;
        recv.x = __shfl_xor_sync(0xffffffffu, send.x, 16);
        recv.y = __shfl_xor_sync(0xffffffffu, send.y, 16);
        a[rbase + i]       = keep;   // rows I already owned
        a[(rbase ^ 8) + i] = recv;   // rows from partner
    }

    // --- input layer 3: stride 8, now local. pair (i,i+8) has rank i ---
#pragma unroll
    for (int i = 0; i < 8; ++i) rot2(a[i], a[i + 8], cs[24 + i]);

    // --- fused bias + smooth relu on rows 0-7 ---
#pragma unroll
    for (int i = 0; i < 8; ++i) {
        float b = sb[i];
        a[i].x = smooth_relu(a[i].x + b);
        a[i].y = smooth_relu(a[i].y + b);
    }

    // --- output layers, strides 1,2,4,8 (all local on 16 rows) ---
    blayer16<1>(a, cs + 32);
    blayer16<2>(a, cs + 40);
    blayer16<4>(a, cs + 48);
    blayer16<8>(a, cs + 56);

    // --- swap back and store coalesced float4 ---
#pragma unroll
    for (int i = 0; i < 8; ++i) {
        float2 send = a[(rbase ^ 8) + i];
        float2 keep = a[rbase + i];
        float2 recv;
        recv.x = __shfl_xor_sync(0xffffffffu, send.x, 16);
        recv.y = __shfl_xor_sync(0xffffffffu, send.y, 16);
        float4 w = half ? make_float4(recv.x, recv.y, keep.x, keep.y)
                        : make_float4(keep.x, keep.y, recv.x, recv.y);
        *reinterpret_cast<float4*>(out + (size_t)rout[rbase + i] * B + col) = w;
    }
}

// ---------------------------------------------------------------------------
// Prep: cos/sin table + coverage marks (one kernel). Copy-uncovered reads
// flags then clears them (state returns to zero every replay; graph-safe).
// ---------------------------------------------------------------------------

__global__ void prep_kernel(const float* __restrict__ angles,
                            const int*   __restrict__ idx_out,
                            int nang, int N)
{
    int i = blockIdx.x * blockDim.x + threadIdx.x;
    if (i < nang) {
        float s, c;
        sincosf(angles[i], &s, &c);
        g_cs[i] = make_float2(c, s);
    }
    if (i < N) g_covered[idx_out[i]] = 1;
}

__global__ __launch_bounds__(256)
void copy_uncovered_kernel(const float* __restrict__ data,
                           float* __restrict__ out, int B) {
    int row = blockIdx.x;
    __shared__ int s_cov;
    if (threadIdx.x == 0) {
        s_cov = g_covered[row];
        g_covered[row] = 0;          // self-reset for next replay
    }
    __syncthreads();
    if (s_cov) return;
    const float4* src = reinterpret_cast<const float4*>(data + (size_t)row * B);
    float4*       dst = reinterpret_cast<float4*>(out + (size_t)row * B);
    for (int i = threadIdx.x; i < (B >> 2); i += blockDim.x)
        dst[i] = src[i];
}

extern "C" void kernel_launch(void* const* d_in, const int* in_sizes, int n_in,
                              void* d_out, int out_size)
{
    const float* data    = (const float*)d_in[0];
    const float* angles  = (const float*)d_in[1];
    const float* biases  = (const float*)d_in[2];
    const int*   idx_in  = (const int*)d_in[3];
    const int*   idx_out = (const int*)d_in[4];
    float*       out     = (float*)d_out;

    const int N    = in_sizes[3];          // gathered rows (4096)
    const int B    = in_sizes[0] / N;      // row width (8192)
    const int R    = out_size / B;         // rows in out
    const int nang = in_sizes[1];          // total angle count

    int prep_n = nang > N ? nang : N;
    prep_kernel<<<(prep_n + 255) / 256, 256>>>(angles, idx_out, nang, N);
    copy_uncovered_kernel<<<R, 256>>>(data, out, B);

    dim3 grid(B / 512, N / 16);
    butterfly_kernel<<<grid, 256>>>(data, biases, idx_in, idx_out, out, N, B);
}

// round 5
// speedup vs baseline: 1.9369x; 1.9369x over previous
#include <cuda_runtime.h>
#include <math.h>

// ---------------------------------------------------------------------------
// Butterfly module, round 5.
//
// Back to R1's proven all-local structure (no shuffles, no exchanges), but
// with a 16-row x float2 per-thread tile (32 data regs instead of R1's 64).
// CTA = 16-row block x 512 cols, 256 threads. All 8 layers + activation are
// thread-local. Streaming cache hints (single-touch 256MB working set).
// ---------------------------------------------------------------------------

#define CURV2 0.01f   // CURVATURE^2 = 0.1^2

__device__ unsigned char g_covered[1 << 20];  // scatter coverage flags (init 0)

__device__ __forceinline__ float smooth_relu(float xa) {
    return 0.5f * (xa + sqrtf(fmaf(xa, xa, CURV2)));
}

__device__ __forceinline__ void rot2(float2& l, float2& h, float2 cs) {
    float2 nl, nh;
    nl.x = fmaf(cs.x, l.x, cs.y * h.x);  nh.x = fmaf(cs.x, h.x, -cs.y * l.x);
    nl.y = fmaf(cs.x, l.y, cs.y * h.y);  nh.y = fmaf(cs.x, h.y, -cs.y * l.y);
    l = nl; h = nh;
}

// One butterfly layer over the 16-row block, compile-time stride S.
// cs: 8 (cos,sin) pairs ordered by ascending low-row offset (R1-validated).
template <int S>
__device__ __forceinline__ void blayer16(float2 a[16], const float2* __restrict__ cs) {
    int p = 0;
#pragma unroll
    for (int o = 0; o < 16; ++o)
        if ((o & S) == 0) { rot2(a[o], a[o + S], cs[p++]); }
}

__global__ __launch_bounds__(256)
void butterfly_kernel(const float* __restrict__ data,
                      const float* __restrict__ angles,
                      const float* __restrict__ biases,
                      const int*   __restrict__ idx_in,
                      const int*   __restrict__ idx_out,
                      float*       __restrict__ out,
                      int N, int B)
{
    __shared__ float2 cs[64];    // [layer 0..7][pair 0..7] -> (cos, sin)
    __shared__ float  sb[8];
    __shared__ int    rin[16], rout[16];

    const int tid = threadIdx.x;
    const int blk = blockIdx.y;

    if (tid < 64) {
        int l = tid >> 3, p = tid & 7;
        float ang = angles[(size_t)l * (N >> 1) + blk * 8 + p];
        float s, c;
        sincosf(ang, &s, &c);
        cs[tid] = make_float2(c, s);
    }
    if (tid < 8)  sb[tid] = biases[blk * 8 + tid];
    if (tid < 16) {
        rin[tid]  = idx_in[blk * 16 + tid];
        rout[tid] = idx_out[blk * 16 + tid];
    }
    __syncthreads();

    const int col = blockIdx.x * 512 + tid * 2;

    // --- load 16 rows x float2 (coalesced: warp covers 256B per row) ---
    float2 a[16];
#pragma unroll
    for (int i = 0; i < 16; ++i)
        a[i] = __ldcs(reinterpret_cast<const float2*>(
                   data + (size_t)rin[i] * B + col));

    // --- input layers: strides 1,2,4,8 ---
    blayer16<1>(a, cs + 0);
    blayer16<2>(a, cs + 8);
    blayer16<4>(a, cs + 16);
    blayer16<8>(a, cs + 24);

    // --- fused bias + smooth relu on rows 0-7 of the block ---
#pragma unroll
    for (int i = 0; i < 8; ++i) {
        float b = sb[i];
        a[i].x = smooth_relu(a[i].x + b);
        a[i].y = smooth_relu(a[i].y + b);
    }

    // --- output layers: strides 1,2,4,8 ---
    blayer16<1>(a, cs + 32);
    blayer16<2>(a, cs + 40);
    blayer16<4>(a, cs + 48);
    blayer16<8>(a, cs + 56);

    // --- store (streaming) ---
#pragma unroll
    for (int i = 0; i < 16; ++i)
        __stcs(reinterpret_cast<float2*>(out + (size_t)rout[i] * B + col), a[i]);
}

// ---------------------------------------------------------------------------
// Rows of `out` NOT targeted by idx_out pass through from `data`.
// mark sets flags; copy reads then CLEARS them (state returns to all-zero
// after every replay -> graph-deterministic).
// ---------------------------------------------------------------------------

__global__ void mark_flags_kernel(const int* __restrict__ idx_out, int N) {
    int i = blockIdx.x * blockDim.x + threadIdx.x;
    if (i < N) g_covered[idx_out[i]] = 1;
}

__global__ __launch_bounds__(256)
void copy_uncovered_kernel(const float* __restrict__ data,
                           float* __restrict__ out, int B, int R) {
    __shared__ unsigned char f[16];
    const int base = blockIdx.x * 16;
    if (threadIdx.x < 16) {
        int r = base + threadIdx.x;
        unsigned char c = (r < R) ? g_covered[r] : 1;
        f[threadIdx.x] = c;
        if (r < R) g_covered[r] = 0;      // self-reset for next replay
    }
    __syncthreads();
#pragma unroll 1
    for (int r = 0; r < 16; ++r) {
        if (f[r]) continue;
        int row = base + r;
        const float4* src = reinterpret_cast<const float4*>(data + (size_t)row * B);
        float4*       dst = reinterpret_cast<float4*>(out + (size_t)row * B);
        for (int i = threadIdx.x; i < (B >> 2); i += blockDim.x)
            dst[i] = src[i];
    }
}

extern "C" void kernel_launch(void* const* d_in, const int* in_sizes, int n_in,
                              void* d_out, int out_size)
{
    const float* data    = (const float*)d_in[0];
    const float* angles  = (const float*)d_in[1];
    const float* biases  = (const float*)d_in[2];
    const int*   idx_in  = (const int*)d_in[3];
    const int*   idx_out = (const int*)d_in[4];
    float*       out     = (float*)d_out;

    const int N = in_sizes[3];            // gathered rows (4096)
    const int B = in_sizes[0] / N;        // row width (8192)
    const int R = out_size / B;           // rows in out

    mark_flags_kernel<<<(N + 255) / 256, 256>>>(idx_out, N);
    copy_uncovered_kernel<<<(R + 15) / 16, 256>>>(data, out, B, R);

    // main fused butterfly: tile = 16 rows x 512 floats
    dim3 grid(B / 512, N / 16);
    butterfly_kernel<<<grid, 256>>>(data, angles, biases, idx_in, idx_out,
                                    out, N, B);
}